// round 1
// baseline (speedup 1.0000x reference)
#include <cuda_runtime.h>
#include <cstdint>

#define D       28
#define EMB     784
#define SLEN    64
#define WPB     4          // warps (sentences) per block
#define NBATCH  2048

// ---- packed f32x2 helpers (Blackwell FFMA2 path, PTX-only) ----
__device__ __forceinline__ unsigned long long ffma2(unsigned long long a,
                                                    unsigned long long b,
                                                    unsigned long long c) {
    unsigned long long d;
    asm("fma.rn.f32x2 %0, %1, %2, %3;" : "=l"(d) : "l"(a), "l"(b), "l"(c));
    return d;
}
__device__ __forceinline__ unsigned long long pack2(float x, float y) {
    unsigned long long d;
    asm("mov.b64 %0, {%1, %2};" : "=l"(d) : "f"(x), "f"(y));
    return d;
}
__device__ __forceinline__ void unpack2(unsigned long long v, float& x, float& y) {
    asm("mov.b64 {%0, %1}, %2;" : "=f"(x), "=f"(y) : "l"(v));
}
__device__ __forceinline__ void cp16(void* dst_smem, const void* src_gmem) {
    unsigned s = (unsigned)__cvta_generic_to_shared(dst_smem);
    asm volatile("cp.async.cg.shared.global [%0], [%1], 16;" :: "r"(s), "l"(src_gmem));
}

__global__ __launch_bounds__(WPB * 32)
void w2m_chain_kernel(const float* __restrict__ table,
                      const int*   __restrict__ sent,
                      float*       __restrict__ out) {
    // warp-private double buffers for the current/next matrix
    __shared__ __align__(16) float sbuf[WPB][2][EMB];

    const int warp = threadIdx.x >> 5;
    const int lane = threadIdx.x & 31;
    const int b    = blockIdx.x * WPB + warp;     // sentence id
    const int* si  = sent + b * SLEN;

    // ---- init cur = M_0 (each of 28 lanes owns one 28-float row) ----
    float c[D];
    {
        const int idx0 = si[0];
        const float* r0 = table + (size_t)idx0 * EMB + lane * D;
        if (lane < D) {
            #pragma unroll
            for (int t = 0; t < 7; t++) {
                float4 v = *(const float4*)(r0 + 4 * t);
                c[4*t] = v.x; c[4*t+1] = v.y; c[4*t+2] = v.z; c[4*t+3] = v.w;
            }
        }
    }

    // ---- prologue: prefetch M_1 into buffer 1 ----
    {
        const int w1 = si[1];
        const float* src = table + (size_t)w1 * EMB;
        float* dst = sbuf[warp][1];
        for (int cc = lane; cc < EMB / 4; cc += 32)
            cp16(dst + 4 * cc, src + 4 * cc);
        asm volatile("cp.async.commit_group;");
    }

    for (int s = 1; s < SLEN; ++s) {
        // prefetch M_{s+1} into the buffer freed at step s-1, overlap with compute
        if (s + 1 < SLEN) {
            const int wn = si[s + 1];
            const float* src = table + (size_t)wn * EMB;
            float* dst = sbuf[warp][(s + 1) & 1];
            for (int cc = lane; cc < EMB / 4; cc += 32)
                cp16(dst + 4 * cc, src + 4 * cc);
            asm volatile("cp.async.commit_group;");
            asm volatile("cp.async.wait_group 1;");   // M_s copy complete
        } else {
            asm volatile("cp.async.wait_group 0;");
        }
        __syncthreads();   // copies visible to all lanes

        const float* m = sbuf[warp][s & 1];
        if (lane < D) {
            unsigned long long acc[D / 2];
            #pragma unroll
            for (int j = 0; j < D / 2; j++) acc[j] = 0ULL;   // {+0.f,+0.f}

            #pragma unroll
            for (int k = 0; k < D; k++) {
                const unsigned long long ck = pack2(c[k], c[k]);
                const ulonglong2* mr = (const ulonglong2*)(m + k * D); // uniform addr -> LDS broadcast
                #pragma unroll
                for (int t = 0; t < 7; t++) {
                    ulonglong2 mv = mr[t];                  // 4 floats: m[k][4t..4t+3]
                    acc[2*t]     = ffma2(ck, mv.x, acc[2*t]);
                    acc[2*t + 1] = ffma2(ck, mv.y, acc[2*t + 1]);
                }
            }
            #pragma unroll
            for (int j = 0; j < D / 2; j++) unpack2(acc[j], c[2*j], c[2*j + 1]);
        }
        __syncthreads();   // all reads of this buffer done before next overwrite
    }

    // ---- store result row ----
    if (lane < D) {
        float* o = out + (size_t)b * EMB + lane * D;
        #pragma unroll
        for (int t = 0; t < 7; t++) {
            float4 v = make_float4(c[4*t], c[4*t+1], c[4*t+2], c[4*t+3]);
            *(float4*)(o + 4 * t) = v;
        }
    }
}

extern "C" void kernel_launch(void* const* d_in, const int* in_sizes, int n_in,
                              void* d_out, int out_size) {
    const float* table = (const float*)d_in[0];   // [32001, 784] fp32
    const int*   sent  = (const int*)d_in[1];     // [2048, 64] int32
    float*       out   = (float*)d_out;           // [2048, 784] fp32

    dim3 grid(NBATCH / WPB);
    dim3 block(WPB * 32);
    w2m_chain_kernel<<<grid, block>>>(table, sent, out);
}

// round 2
// speedup vs baseline: 1.1049x; 1.1049x over previous
#include <cuda_runtime.h>
#include <cstdint>

#define D       28
#define EMB     784
#define SLEN    64
#define NW      8          // warps per block (one sentence per block)
#define SEG     8          // matrices per warp segment
#define NBATCH  2048

// ---- packed f32x2 helpers (Blackwell FFMA2 path, PTX-only) ----
__device__ __forceinline__ unsigned long long ffma2(unsigned long long a,
                                                    unsigned long long b,
                                                    unsigned long long c) {
    unsigned long long d;
    asm("fma.rn.f32x2 %0, %1, %2, %3;" : "=l"(d) : "l"(a), "l"(b), "l"(c));
    return d;
}
__device__ __forceinline__ unsigned long long pack2(float x, float y) {
    unsigned long long d;
    asm("mov.b64 %0, {%1, %2};" : "=l"(d) : "f"(x), "f"(y));
    return d;
}
__device__ __forceinline__ void unpack2(unsigned long long v, float& x, float& y) {
    asm("mov.b64 {%0, %1}, %2;" : "=f"(x), "=f"(y) : "l"(v));
}
__device__ __forceinline__ void cp16(void* dst_smem, const void* src_gmem) {
    unsigned s = (unsigned)__cvta_generic_to_shared(dst_smem);
    asm volatile("cp.async.cg.shared.global [%0], [%1], 16;" :: "r"(s), "l"(src_gmem));
}

// c (row `lane` of cur, 28 floats in regs)  <-  c @ M, M broadcast from smem
__device__ __forceinline__ void mat_mul_row(float c[D], const float* __restrict__ m,
                                            int lane) {
    if (lane < D) {
        unsigned long long acc[D / 2];
        #pragma unroll
        for (int j = 0; j < D / 2; j++) acc[j] = 0ULL;
        #pragma unroll
        for (int k = 0; k < D; k++) {
            const unsigned long long ck = pack2(c[k], c[k]);
            const ulonglong2* mr = (const ulonglong2*)(m + k * D); // uniform -> broadcast
            #pragma unroll
            for (int t = 0; t < 7; t++) {
                ulonglong2 mv = mr[t];
                acc[2*t]     = ffma2(ck, mv.x, acc[2*t]);
                acc[2*t + 1] = ffma2(ck, mv.y, acc[2*t + 1]);
            }
        }
        #pragma unroll
        for (int j = 0; j < D / 2; j++) unpack2(acc[j], c[2*j], c[2*j + 1]);
    }
}

__device__ __forceinline__ void store_rows(const float c[D], float* dst, int lane) {
    if (lane < D) {
        float* o = dst + lane * D;
        #pragma unroll
        for (int t = 0; t < 7; t++)
            *(float4*)(o + 4 * t) = make_float4(c[4*t], c[4*t+1], c[4*t+2], c[4*t+3]);
    }
}

__global__ __launch_bounds__(NW * 32)
void w2m_chain_kernel(const float* __restrict__ table,
                      const int*   __restrict__ sent,
                      float*       __restrict__ out) {
    // warp-private double buffers; reused as partial-product storage in the tree
    __shared__ __align__(16) float sbuf[NW][2][EMB];

    const int warp = threadIdx.x >> 5;
    const int lane = threadIdx.x & 31;
    const int b    = blockIdx.x;                  // sentence id
    const int* si  = sent + b * SLEN + warp * SEG;

    // ---- segment phase: cur = M_{8w} @ ... @ M_{8w+7} ----
    float c[D];
    {   // cur = first matrix of segment, straight from gmem
        const float* r0 = table + (size_t)si[0] * EMB + lane * D;
        if (lane < D) {
            #pragma unroll
            for (int t = 0; t < 7; t++) {
                float4 v = *(const float4*)(r0 + 4 * t);
                c[4*t] = v.x; c[4*t+1] = v.y; c[4*t+2] = v.z; c[4*t+3] = v.w;
            }
        }
    }
    {   // prefetch second matrix
        const float* src = table + (size_t)si[1] * EMB;
        float* dst = sbuf[warp][1];
        for (int cc = lane; cc < EMB / 4; cc += 32) cp16(dst + 4 * cc, src + 4 * cc);
        asm volatile("cp.async.commit_group;");
    }

    for (int s = 1; s < SEG; ++s) {
        if (s + 1 < SEG) {
            const float* src = table + (size_t)si[s + 1] * EMB;
            float* dst = sbuf[warp][(s + 1) & 1];
            for (int cc = lane; cc < EMB / 4; cc += 32) cp16(dst + 4 * cc, src + 4 * cc);
            asm volatile("cp.async.commit_group;");
            asm volatile("cp.async.wait_group 1;");   // M_s is complete
        } else {
            asm volatile("cp.async.wait_group 0;");
        }
        __syncwarp();                                 // buffer warp-private: warp sync only
        mat_mul_row(c, sbuf[warp][s & 1], lane);
        __syncwarp();                                 // reads done before next overwrite
    }

    // ---- tree combine: (((P0 P1)(P2 P3))((P4 P5)(P6 P7))) ----
    // odd warps publish partials; even warps keep theirs in registers
    if (warp & 1) store_rows(c, sbuf[warp][0], lane);
    __syncthreads();

    if ((warp & 1) == 0) {
        mat_mul_row(c, sbuf[warp + 1][0], lane);      // Q = P_w @ P_{w+1}
        if (warp == 2 || warp == 6) store_rows(c, sbuf[warp][0], lane);
    }
    __syncthreads();

    if (warp == 0 || warp == 4) {
        mat_mul_row(c, sbuf[warp + 2][0], lane);      // R = Q @ Q'
        if (warp == 4) store_rows(c, sbuf[4][0], lane);
    }
    __syncthreads();

    if (warp == 0) {
        mat_mul_row(c, sbuf[4][0], lane);             // final = R0 @ R1
        store_rows(c, out + (size_t)b * EMB, lane);
    }
}

extern "C" void kernel_launch(void* const* d_in, const int* in_sizes, int n_in,
                              void* d_out, int out_size) {
    const float* table = (const float*)d_in[0];   // [32001, 784] fp32
    const int*   sent  = (const int*)d_in[1];     // [2048, 64]  int32
    float*       out   = (float*)d_out;           // [2048, 784] fp32

    w2m_chain_kernel<<<NBATCH, NW * 32>>>(table, sent, out);
}

// round 3
// speedup vs baseline: 1.1058x; 1.0008x over previous
#include <cuda_runtime.h>
#include <cstdint>

#define D       28
#define EMB     784
#define MATB    (EMB * 4)   // 3136 bytes per matrix
#define SLEN    64
#define NW      8           // warps per block (one sentence per block)
#define SEG     8           // matrices per warp segment
#define NBATCH  2048

// ---- packed f32x2 helpers (Blackwell FFMA2 path, PTX-only) ----
__device__ __forceinline__ unsigned long long ffma2(unsigned long long a,
                                                    unsigned long long b,
                                                    unsigned long long c) {
    unsigned long long d;
    asm("fma.rn.f32x2 %0, %1, %2, %3;" : "=l"(d) : "l"(a), "l"(b), "l"(c));
    return d;
}
__device__ __forceinline__ unsigned long long pack2(float x, float y) {
    unsigned long long d;
    asm("mov.b64 %0, {%1, %2};" : "=l"(d) : "f"(x), "f"(y));
    return d;
}
__device__ __forceinline__ void unpack2(unsigned long long v, float& x, float& y) {
    asm("mov.b64 {%0, %1}, %2;" : "=f"(x), "=f"(y) : "l"(v));
}

__device__ __forceinline__ unsigned smem_u32(const void* p) {
    return (unsigned)__cvta_generic_to_shared(p);
}
__device__ __forceinline__ void mbar_init(unsigned a, unsigned cnt) {
    asm volatile("mbarrier.init.shared.b64 [%0], %1;" :: "r"(a), "r"(cnt) : "memory");
}
__device__ __forceinline__ void mbar_expect_tx(unsigned a, unsigned bytes) {
    asm volatile("mbarrier.arrive.expect_tx.shared.b64 _, [%0], %1;"
                 :: "r"(a), "r"(bytes) : "memory");
}
__device__ __forceinline__ void bulk_g2s(unsigned dst, const void* src, unsigned bytes,
                                         unsigned mbar) {
    asm volatile("cp.async.bulk.shared::cta.global.mbarrier::complete_tx::bytes "
                 "[%0], [%1], %2, [%3];"
                 :: "r"(dst), "l"(src), "r"(bytes), "r"(mbar) : "memory");
}
__device__ __forceinline__ void mbar_wait(unsigned a, unsigned parity) {
    unsigned done;
    asm volatile(
        "{\n\t.reg .pred p;\n\t"
        "mbarrier.try_wait.parity.shared.b64 p, [%1], %2;\n\t"
        "selp.b32 %0, 1, 0, p;\n\t}"
        : "=r"(done) : "r"(a), "r"(parity) : "memory");
    while (!done) {
        asm volatile(
            "{\n\t.reg .pred p;\n\t"
            "mbarrier.try_wait.parity.shared.b64 p, [%1], %2, 0x989680;\n\t"
            "selp.b32 %0, 1, 0, p;\n\t}"
            : "=r"(done) : "r"(a), "r"(parity) : "memory");
    }
}

// c (row `lane` of cur, 28 floats in regs)  <-  c @ M, M broadcast from smem
__device__ __forceinline__ void mat_mul_row(float c[D], const float* __restrict__ m,
                                            int lane) {
    if (lane < D) {
        unsigned long long acc[D / 2];
        #pragma unroll
        for (int j = 0; j < D / 2; j++) acc[j] = 0ULL;
        #pragma unroll
        for (int k = 0; k < D; k++) {
            const unsigned long long ck = pack2(c[k], c[k]);
            const ulonglong2* mr = (const ulonglong2*)(m + k * D); // uniform -> broadcast
            #pragma unroll
            for (int t = 0; t < 7; t++) {
                ulonglong2 mv = mr[t];
                acc[2*t]     = ffma2(ck, mv.x, acc[2*t]);
                acc[2*t + 1] = ffma2(ck, mv.y, acc[2*t + 1]);
            }
        }
        #pragma unroll
        for (int j = 0; j < D / 2; j++) unpack2(acc[j], c[2*j], c[2*j + 1]);
    }
}

__device__ __forceinline__ void store_rows(const float c[D], float* dst, int lane) {
    if (lane < D) {
        float* o = dst + lane * D;
        #pragma unroll
        for (int t = 0; t < 7; t++)
            *(float4*)(o + 4 * t) = make_float4(c[4*t], c[4*t+1], c[4*t+2], c[4*t+3]);
    }
}

__global__ __launch_bounds__(NW * 32)
void w2m_chain_kernel(const float* __restrict__ table,
                      const int*   __restrict__ sent,
                      float*       __restrict__ out) {
    // warp-private double buffers; reused as partial-product storage in the tree
    __shared__ __align__(16) float sbuf[NW][2][EMB];
    __shared__ __align__(8)  unsigned long long mbar[NW][2];

    const int warp = threadIdx.x >> 5;
    const int lane = threadIdx.x & 31;
    const int b    = blockIdx.x;                  // sentence id
    const int* si  = sent + b * SLEN + warp * SEG;

    // init all per-warp mbarriers (arrive count = 1: one expect_tx producer)
    if (threadIdx.x < NW * 2)
        mbar_init(smem_u32(&mbar[threadIdx.x >> 1][threadIdx.x & 1]), 1);
    __syncthreads();

    const unsigned mb0 = smem_u32(&mbar[warp][0]);
    const unsigned mb1 = smem_u32(&mbar[warp][1]);
    const unsigned sb0 = smem_u32(&sbuf[warp][0][0]);
    const unsigned sb1 = smem_u32(&sbuf[warp][1][0]);

    // ---- segment phase: cur = M_{8w} @ ... @ M_{8w+7} ----
    float c[D];
    {   // cur = first matrix of segment, straight from gmem
        const float* r0 = table + (size_t)si[0] * EMB + lane * D;
        if (lane < D) {
            #pragma unroll
            for (int t = 0; t < 7; t++) {
                float4 v = __ldg((const float4*)(r0 + 4 * t));
                c[4*t] = v.x; c[4*t+1] = v.y; c[4*t+2] = v.z; c[4*t+3] = v.w;
            }
        }
    }
    // prefetch second matrix via TMA bulk
    if (lane == 0) {
        mbar_expect_tx(mb1, MATB);
        bulk_g2s(sb1, table + (size_t)si[1] * EMB, MATB, mb1);
    }

    int ph0 = 0, ph1 = 0;
    #pragma unroll 1
    for (int s = 1; s < SEG; ++s) {
        // prefetch M_{s+1} into the buffer last read at step s-1
        if (s + 1 < SEG && lane == 0) {
            const unsigned mbn = ((s + 1) & 1) ? mb1 : mb0;
            const unsigned sbn = ((s + 1) & 1) ? sb1 : sb0;
            mbar_expect_tx(mbn, MATB);
            bulk_g2s(sbn, table + (size_t)si[s + 1] * EMB, MATB, mbn);
        }
        // wait for M_s
        if (s & 1) { mbar_wait(mb1, ph1); ph1 ^= 1; }
        else       { mbar_wait(mb0, ph0); ph0 ^= 1; }

        mat_mul_row(c, sbuf[warp][s & 1], lane);
        __syncwarp();
    }

    // ---- tree combine: (((P0 P1)(P2 P3))((P4 P5)(P6 P7))) ----
    if (warp & 1) store_rows(c, sbuf[warp][0], lane);
    __syncthreads();

    if ((warp & 1) == 0) {
        mat_mul_row(c, sbuf[warp + 1][0], lane);      // Q = P_w @ P_{w+1}
        if (warp == 2 || warp == 6) store_rows(c, sbuf[warp][0], lane);
    }
    __syncthreads();

    if (warp == 0 || warp == 4) {
        mat_mul_row(c, sbuf[warp + 2][0], lane);      // R = Q @ Q'
        if (warp == 4) store_rows(c, sbuf[4][0], lane);
    }
    __syncthreads();

    if (warp == 0) {
        mat_mul_row(c, sbuf[4][0], lane);             // final = R0 @ R1
        store_rows(c, out + (size_t)b * EMB, lane);
    }
}

extern "C" void kernel_launch(void* const* d_in, const int* in_sizes, int n_in,
                              void* d_out, int out_size) {
    const float* table = (const float*)d_in[0];   // [32001, 784] fp32
    const int*   sent  = (const int*)d_in[1];     // [2048, 64]  int32
    float*       out   = (float*)d_out;           // [2048, 784] fp32

    w2m_chain_kernel<<<NBATCH, NW * 32>>>(table, sent, out);
}

// round 4
// speedup vs baseline: 1.4125x; 1.2774x over previous
#include <cuda_runtime.h>
#include <cstdint>

#define D       28
#define EMB     784
#define MATB    (EMB * 4)    // 3136 bytes per matrix
#define SLEN    64
#define HALF    32           // words per chain (2 chains per warp)
#define NBATCH  2048

// smem slot offsets in floats. Slot stride 792 floats (3168 B).
// B-base - A-base = 2*3168 = 6336 B == 64 (mod 128)  -> the two broadcast
// addresses of a dual LDS.128 land on disjoint bank groups: conflict-free.
#define S_A0    0
#define S_A1    792
#define S_B0    1584
#define S_B1    2376
#define SMEMF   3168

// ---- packed f32x2 helpers (Blackwell FFMA2 path, PTX-only) ----
__device__ __forceinline__ unsigned long long ffma2(unsigned long long a,
                                                    unsigned long long b,
                                                    unsigned long long c) {
    unsigned long long d;
    asm("fma.rn.f32x2 %0, %1, %2, %3;" : "=l"(d) : "l"(a), "l"(b), "l"(c));
    return d;
}
__device__ __forceinline__ unsigned long long pack2(float x, float y) {
    unsigned long long d;
    asm("mov.b64 %0, {%1, %2};" : "=l"(d) : "f"(x), "f"(y));
    return d;
}
__device__ __forceinline__ void unpack2(unsigned long long v, float& x, float& y) {
    asm("mov.b64 {%0, %1}, %2;" : "=f"(x), "=f"(y) : "l"(v));
}

__device__ __forceinline__ unsigned smem_u32(const void* p) {
    return (unsigned)__cvta_generic_to_shared(p);
}
__device__ __forceinline__ void mbar_init(unsigned a, unsigned cnt) {
    asm volatile("mbarrier.init.shared.b64 [%0], %1;" :: "r"(a), "r"(cnt) : "memory");
}
__device__ __forceinline__ void mbar_expect_tx(unsigned a, unsigned bytes) {
    asm volatile("mbarrier.arrive.expect_tx.shared.b64 _, [%0], %1;"
                 :: "r"(a), "r"(bytes) : "memory");
}
__device__ __forceinline__ void bulk_g2s(unsigned dst, const void* src, unsigned bytes,
                                         unsigned mbar) {
    asm volatile("cp.async.bulk.shared::cta.global.mbarrier::complete_tx::bytes "
                 "[%0], [%1], %2, [%3];"
                 :: "r"(dst), "l"(src), "r"(bytes), "r"(mbar) : "memory");
}
__device__ __forceinline__ void mbar_wait(unsigned a, unsigned parity) {
    unsigned done;
    asm volatile(
        "{\n\t.reg .pred p;\n\t"
        "mbarrier.try_wait.parity.shared.b64 p, [%1], %2;\n\t"
        "selp.b32 %0, 1, 0, p;\n\t}"
        : "=r"(done) : "r"(a), "r"(parity) : "memory");
    while (!done) {
        asm volatile(
            "{\n\t.reg .pred p;\n\t"
            "mbarrier.try_wait.parity.shared.b64 p, [%1], %2, 0x989680;\n\t"
            "selp.b32 %0, 1, 0, p;\n\t}"
            : "=r"(done) : "r"(a), "r"(parity) : "memory");
    }
}

// Dual-row matmul step: this lane's rows (c0 = row g, c1 = row g+14 of its
// chain) are multiplied by M (per-lane base: chain A lanes read M_A, chain B
// lanes read M_B). Each LDS.128 feeds 4 FFMA2.
__device__ __forceinline__ void mat_mul_dual(float c0[D], float c1[D],
                                             const float* __restrict__ m) {
    unsigned long long a0[D / 2], a1[D / 2];
    #pragma unroll
    for (int j = 0; j < D / 2; j++) { a0[j] = 0ULL; a1[j] = 0ULL; }
    #pragma unroll
    for (int k = 0; k < D; k++) {
        const unsigned long long k0 = pack2(c0[k], c0[k]);
        const unsigned long long k1 = pack2(c1[k], c1[k]);
        const ulonglong2* mr = (const ulonglong2*)(m + k * D);
        #pragma unroll
        for (int t = 0; t < 7; t++) {
            ulonglong2 mv = mr[t];
            a0[2*t]     = ffma2(k0, mv.x, a0[2*t]);
            a0[2*t + 1] = ffma2(k0, mv.y, a0[2*t + 1]);
            a1[2*t]     = ffma2(k1, mv.x, a1[2*t]);
            a1[2*t + 1] = ffma2(k1, mv.y, a1[2*t + 1]);
        }
    }
    #pragma unroll
    for (int j = 0; j < D / 2; j++) {
        unpack2(a0[j], c0[2*j], c0[2*j + 1]);
        unpack2(a1[j], c1[2*j], c1[2*j + 1]);
    }
}

// Mono matmul (row per lane, uniform broadcast of M) for the final combine.
__device__ __forceinline__ void mat_mul_row(float c[D], const float* __restrict__ m,
                                            int lane) {
    if (lane < D) {
        unsigned long long acc[D / 2];
        #pragma unroll
        for (int j = 0; j < D / 2; j++) acc[j] = 0ULL;
        #pragma unroll
        for (int k = 0; k < D; k++) {
            const unsigned long long ck = pack2(c[k], c[k]);
            const ulonglong2* mr = (const ulonglong2*)(m + k * D);
            #pragma unroll
            for (int t = 0; t < 7; t++) {
                ulonglong2 mv = mr[t];
                acc[2*t]     = ffma2(ck, mv.x, acc[2*t]);
                acc[2*t + 1] = ffma2(ck, mv.y, acc[2*t + 1]);
            }
        }
        #pragma unroll
        for (int j = 0; j < D / 2; j++) unpack2(acc[j], c[2*j], c[2*j + 1]);
    }
}

__global__ __launch_bounds__(32)
void w2m_chain_kernel(const float* __restrict__ table,
                      const int*   __restrict__ sent,
                      float*       __restrict__ out) {
    __shared__ __align__(16) float sm[SMEMF];
    __shared__ __align__(8)  unsigned long long mbar[2];

    const int lane = threadIdx.x;
    const int b    = blockIdx.x;
    const int* si  = sent + b * SLEN;

    if (lane < 2) mbar_init(smem_u32(&mbar[lane]), 1);
    __syncwarp();

    const int  grp   = (lane >= 14) ? 1 : 0;                    // 0: chain A, 1: chain B
    const int  g     = (lane < 14) ? lane : (lane < 28 ? lane - 14 : 0);
    const bool valid = (lane < 28);

    // ---- init: cur = first matrix of the chain (rows g and g+14) ----
    float c0[D], c1[D];
    {
        const int w0 = grp ? si[HALF] : si[0];
        const float* p0 = table + (size_t)w0 * EMB + g * D;
        const float* p1 = p0 + 14 * D;
        #pragma unroll
        for (int t = 0; t < 7; t++) {
            float4 v0 = __ldg((const float4*)(p0 + 4 * t));
            float4 v1 = __ldg((const float4*)(p1 + 4 * t));
            c0[4*t] = v0.x; c0[4*t+1] = v0.y; c0[4*t+2] = v0.z; c0[4*t+3] = v0.w;
            c1[4*t] = v1.x; c1[4*t+1] = v1.y; c1[4*t+2] = v1.z; c1[4*t+3] = v1.w;
        }
    }

    // ---- prologue: prefetch step-1 matrices (both chains) into parity-1 ----
    if (lane == 0) {
        const unsigned mb = smem_u32(&mbar[1]);
        mbar_expect_tx(mb, 2 * MATB);
        bulk_g2s(smem_u32(&sm[S_A1]), table + (size_t)si[1] * EMB, MATB, mb);
        bulk_g2s(smem_u32(&sm[S_B1]), table + (size_t)si[HALF + 1] * EMB, MATB, mb);
    }

    int ph0 = 0, ph1 = 0;
    #pragma unroll 1
    for (int s = 1; s < HALF; ++s) {
        const int par = s & 1;
        // prefetch s+1 into the opposite-parity buffers (last read at s-1)
        if (s + 1 < HALF && lane == 0) {
            const int np = (s + 1) & 1;
            const unsigned mb = smem_u32(&mbar[np]);
            mbar_expect_tx(mb, 2 * MATB);
            bulk_g2s(smem_u32(&sm[np ? S_A1 : S_A0]),
                     table + (size_t)si[s + 1] * EMB, MATB, mb);
            bulk_g2s(smem_u32(&sm[np ? S_B1 : S_B0]),
                     table + (size_t)si[HALF + s + 1] * EMB, MATB, mb);
        }
        // wait for step-s matrices
        if (par) { mbar_wait(smem_u32(&mbar[1]), ph1); ph1 ^= 1; }
        else     { mbar_wait(smem_u32(&mbar[0]), ph0); ph0 ^= 1; }

        const float* m = sm + (grp ? (par ? S_B1 : S_B0) : (par ? S_A1 : S_A0));
        mat_mul_dual(c0, c1, m);
        __syncwarp();   // all reads done before this buffer is refilled
    }

    // ---- tail: P = P_A @ P_B (mono) ----
    // publish both partials to smem (A -> slot A0, B -> slot B0)
    if (valid) {
        float* dst = sm + (grp ? S_B0 : S_A0);
        float* r0 = dst + g * D;
        float* r1 = dst + (g + 14) * D;
        #pragma unroll
        for (int t = 0; t < 7; t++) {
            *(float4*)(r0 + 4 * t) = make_float4(c0[4*t], c0[4*t+1], c0[4*t+2], c0[4*t+3]);
            *(float4*)(r1 + 4 * t) = make_float4(c1[4*t], c1[4*t+1], c1[4*t+2], c1[4*t+3]);
        }
    }
    __syncwarp();

    float c[D];
    if (lane < D) {
        const float* p = sm + S_A0 + lane * D;
        #pragma unroll
        for (int t = 0; t < 7; t++) {
            float4 v = *(const float4*)(p + 4 * t);
            c[4*t] = v.x; c[4*t+1] = v.y; c[4*t+2] = v.z; c[4*t+3] = v.w;
        }
    }
    mat_mul_row(c, sm + S_B0, lane);

    if (lane < D) {
        float* o = out + (size_t)b * EMB + lane * D;
        #pragma unroll
        for (int t = 0; t < 7; t++)
            *(float4*)(o + 4 * t) = make_float4(c[4*t], c[4*t+1], c[4*t+2], c[4*t+3]);
    }
}

extern "C" void kernel_launch(void* const* d_in, const int* in_sizes, int n_in,
                              void* d_out, int out_size) {
    const float* table = (const float*)d_in[0];   // [32001, 784] fp32
    const int*   sent  = (const int*)d_in[1];     // [2048, 64]  int32
    float*       out   = (float*)d_out;           // [2048, 784] fp32

    w2m_chain_kernel<<<NBATCH, 32>>>(table, sent, out);
}

// round 5
// speedup vs baseline: 1.4339x; 1.0152x over previous
#include <cuda_runtime.h>
#include <cstdint>

#define D       28
#define EMB     784
#define MATB    (EMB * 4)    // 3136 bytes per matrix
#define SLEN    64
#define HALF    32           // words per chain (2 chains per warp)
#define NBATCH  2048

// smem slot offsets in floats. Slot stride 792 floats (3168 B).
// B-base - A-base = 2*3168 = 6336 B == 64 (mod 128)  -> the two broadcast
// addresses of a dual LDS.128 land on disjoint bank groups: conflict-free.
#define S_A0    0
#define S_A1    792
#define S_B0    1584
#define S_B1    2376
#define SMEMF   3168

// ---- packed f32x2 helpers (Blackwell FFMA2 path, PTX-only) ----
__device__ __forceinline__ unsigned long long ffma2(unsigned long long a,
                                                    unsigned long long b,
                                                    unsigned long long c) {
    unsigned long long d;
    asm("fma.rn.f32x2 %0, %1, %2, %3;" : "=l"(d) : "l"(a), "l"(b), "l"(c));
    return d;
}
__device__ __forceinline__ unsigned long long pack2(float x, float y) {
    unsigned long long d;
    asm("mov.b64 %0, {%1, %2};" : "=l"(d) : "f"(x), "f"(y));
    return d;
}
__device__ __forceinline__ void unpack2(unsigned long long v, float& x, float& y) {
    asm("mov.b64 {%0, %1}, %2;" : "=f"(x), "=f"(y) : "l"(v));
}

__device__ __forceinline__ unsigned smem_u32(const void* p) {
    return (unsigned)__cvta_generic_to_shared(p);
}
__device__ __forceinline__ void mbar_init(unsigned a, unsigned cnt) {
    asm volatile("mbarrier.init.shared.b64 [%0], %1;" :: "r"(a), "r"(cnt) : "memory");
}
__device__ __forceinline__ void mbar_expect_tx(unsigned a, unsigned bytes) {
    asm volatile("mbarrier.arrive.expect_tx.shared.b64 _, [%0], %1;"
                 :: "r"(a), "r"(bytes) : "memory");
}
__device__ __forceinline__ void bulk_g2s(unsigned dst, const void* src, unsigned bytes,
                                         unsigned mbar) {
    asm volatile("cp.async.bulk.shared::cta.global.mbarrier::complete_tx::bytes "
                 "[%0], [%1], %2, [%3];"
                 :: "r"(dst), "l"(src), "r"(bytes), "r"(mbar) : "memory");
}
__device__ __forceinline__ void mbar_wait(unsigned a, unsigned parity) {
    unsigned done;
    asm volatile(
        "{\n\t.reg .pred p;\n\t"
        "mbarrier.try_wait.parity.shared.b64 p, [%1], %2;\n\t"
        "selp.b32 %0, 1, 0, p;\n\t}"
        : "=r"(done) : "r"(a), "r"(parity) : "memory");
    while (!done) {
        asm volatile(
            "{\n\t.reg .pred p;\n\t"
            "mbarrier.try_wait.parity.shared.b64 p, [%1], %2, 0x989680;\n\t"
            "selp.b32 %0, 1, 0, p;\n\t}"
            : "=r"(done) : "r"(a), "r"(parity) : "memory");
    }
}

// Dual-row matmul step, software-pipelined: the 7 LDS.128 of row k+1 are
// issued immediately after each slot's last consumer in row k, so every
// load has a full iteration (~60+ cyc) to complete before use.
__device__ __forceinline__ void mat_mul_dual(float c0[D], float c1[D],
                                             const float* __restrict__ m) {
    unsigned long long a0[D / 2], a1[D / 2];
    ulonglong2 mv[7];
    #pragma unroll
    for (int t = 0; t < 7; t++) mv[t] = ((const ulonglong2*)m)[t];     // row k=0
    #pragma unroll
    for (int j = 0; j < D / 2; j++) { a0[j] = 0ULL; a1[j] = 0ULL; }

    #pragma unroll
    for (int k = 0; k < D; k++) {
        const unsigned long long k0 = pack2(c0[k], c0[k]);
        const unsigned long long k1 = pack2(c1[k], c1[k]);
        const ulonglong2* nxt = (const ulonglong2*)(m + (k + 1) * D);
        #pragma unroll
        for (int t = 0; t < 7; t++) {
            const ulonglong2 cur = mv[t];
            if (k < D - 1) mv[t] = nxt[t];          // prefetch row k+1, slot t
            a0[2*t]     = ffma2(k0, cur.x, a0[2*t]);
            a0[2*t + 1] = ffma2(k0, cur.y, a0[2*t + 1]);
            a1[2*t]     = ffma2(k1, cur.x, a1[2*t]);
            a1[2*t + 1] = ffma2(k1, cur.y, a1[2*t + 1]);
        }
    }
    #pragma unroll
    for (int j = 0; j < D / 2; j++) {
        unpack2(a0[j], c0[2*j], c0[2*j + 1]);
        unpack2(a1[j], c1[2*j], c1[2*j + 1]);
    }
}

// Mono matmul (row per lane, uniform broadcast of M) for the final combine.
__device__ __forceinline__ void mat_mul_row(float c[D], const float* __restrict__ m,
                                            int lane) {
    if (lane < D) {
        unsigned long long acc[D / 2];
        #pragma unroll
        for (int j = 0; j < D / 2; j++) acc[j] = 0ULL;
        #pragma unroll
        for (int k = 0; k < D; k++) {
            const unsigned long long ck = pack2(c[k], c[k]);
            const ulonglong2* mr = (const ulonglong2*)(m + k * D);
            #pragma unroll
            for (int t = 0; t < 7; t++) {
                ulonglong2 mv = mr[t];
                acc[2*t]     = ffma2(ck, mv.x, acc[2*t]);
                acc[2*t + 1] = ffma2(ck, mv.y, acc[2*t + 1]);
            }
        }
        #pragma unroll
        for (int j = 0; j < D / 2; j++) unpack2(acc[j], c[2*j], c[2*j + 1]);
    }
}

__global__ __launch_bounds__(32, 14)
void w2m_chain_kernel(const float* __restrict__ table,
                      const int*   __restrict__ sent,
                      float*       __restrict__ out) {
    __shared__ __align__(16) float sm[SMEMF];
    __shared__ __align__(8)  unsigned long long mbar[2];

    const int lane = threadIdx.x;
    const int b    = blockIdx.x;
    const int* si  = sent + b * SLEN;

    if (lane < 2) mbar_init(smem_u32(&mbar[lane]), 1);
    __syncwarp();

    const int  grp   = (lane >= 14) ? 1 : 0;                    // 0: chain A, 1: chain B
    const int  g     = (lane < 14) ? lane : (lane < 28 ? lane - 14 : 0);
    const bool valid = (lane < 28);

    // ---- init: cur = first matrix of the chain (rows g and g+14) ----
    float c0[D], c1[D];
    {
        const int w0 = grp ? si[HALF] : si[0];
        const float* p0 = table + (size_t)w0 * EMB + g * D;
        const float* p1 = p0 + 14 * D;
        #pragma unroll
        for (int t = 0; t < 7; t++) {
            float4 v0 = __ldg((const float4*)(p0 + 4 * t));
            float4 v1 = __ldg((const float4*)(p1 + 4 * t));
            c0[4*t] = v0.x; c0[4*t+1] = v0.y; c0[4*t+2] = v0.z; c0[4*t+3] = v0.w;
            c1[4*t] = v1.x; c1[4*t+1] = v1.y; c1[4*t+2] = v1.z; c1[4*t+3] = v1.w;
        }
    }

    // ---- prologue: prefetch step-1 matrices (both chains) into parity-1 ----
    if (lane == 0) {
        const unsigned mb = smem_u32(&mbar[1]);
        mbar_expect_tx(mb, 2 * MATB);
        bulk_g2s(smem_u32(&sm[S_A1]), table + (size_t)si[1] * EMB, MATB, mb);
        bulk_g2s(smem_u32(&sm[S_B1]), table + (size_t)si[HALF + 1] * EMB, MATB, mb);
    }

    int ph0 = 0, ph1 = 0;
    #pragma unroll 1
    for (int s = 1; s < HALF; ++s) {
        const int par = s & 1;
        // prefetch s+1 into the opposite-parity buffers (last read at s-1)
        if (s + 1 < HALF && lane == 0) {
            const int np = (s + 1) & 1;
            const unsigned mb = smem_u32(&mbar[np]);
            mbar_expect_tx(mb, 2 * MATB);
            bulk_g2s(smem_u32(&sm[np ? S_A1 : S_A0]),
                     table + (size_t)si[s + 1] * EMB, MATB, mb);
            bulk_g2s(smem_u32(&sm[np ? S_B1 : S_B0]),
                     table + (size_t)si[HALF + s + 1] * EMB, MATB, mb);
        }
        // wait for step-s matrices
        if (par) { mbar_wait(smem_u32(&mbar[1]), ph1); ph1 ^= 1; }
        else     { mbar_wait(smem_u32(&mbar[0]), ph0); ph0 ^= 1; }

        const float* m = sm + (grp ? (par ? S_B1 : S_B0) : (par ? S_A1 : S_A0));
        mat_mul_dual(c0, c1, m);
        __syncwarp();   // all reads done before this buffer is refilled
    }

    // ---- tail: P = P_A @ P_B (mono) ----
    if (valid) {
        float* dst = sm + (grp ? S_B0 : S_A0);
        float* r0 = dst + g * D;
        float* r1 = dst + (g + 14) * D;
        #pragma unroll
        for (int t = 0; t < 7; t++) {
            *(float4*)(r0 + 4 * t) = make_float4(c0[4*t], c0[4*t+1], c0[4*t+2], c0[4*t+3]);
            *(float4*)(r1 + 4 * t) = make_float4(c1[4*t], c1[4*t+1], c1[4*t+2], c1[4*t+3]);
        }
    }
    __syncwarp();

    float c[D];
    if (lane < D) {
        const float* p = sm + S_A0 + lane * D;
        #pragma unroll
        for (int t = 0; t < 7; t++) {
            float4 v = *(const float4*)(p + 4 * t);
            c[4*t] = v.x; c[4*t+1] = v.y; c[4*t+2] = v.z; c[4*t+3] = v.w;
        }
    }
    mat_mul_row(c, sm + S_B0, lane);

    if (lane < D) {
        float* o = out + (size_t)b * EMB + lane * D;
        #pragma unroll
        for (int t = 0; t < 7; t++)
            *(float4*)(o + 4 * t) = make_float4(c[4*t], c[4*t+1], c[4*t+2], c[4*t+3]);
    }
}

extern "C" void kernel_launch(void* const* d_in, const int* in_sizes, int n_in,
                              void* d_out, int out_size) {
    const float* table = (const float*)d_in[0];   // [32001, 784] fp32
    const int*   sent  = (const int*)d_in[1];     // [2048, 64]  int32
    float*       out   = (float*)d_out;           // [2048, 784] fp32

    w2m_chain_kernel<<<NBATCH, 32>>>(table, sent, out);
}